// round 15
// baseline (speedup 1.0000x reference)
#include <cuda_runtime.h>
#include <cuda_fp16.h>
#include <cstdint>

#define M_TOK   8192
#define DIN     4096
#define DOUT    4096
#define RNK     64
#define NEXP    16
#define SCALING 0.5f
#define NSPLIT  8

// ---------------- scratch (static device globals; no allocations) -----------
__device__ __half g_x  [(size_t)M_TOK * DIN];    // 64 MB  x fp16 row-major
__device__ __half g_w  [(size_t)DOUT * DIN];     // 32 MB  base_w fp16
__device__ __half g_wb [(size_t)NEXP * DOUT * RNK]; // 8 MB  B fp16 [e][o][r]
__device__ __half g_w2 [128 * DIN];              //  1 MB  [A; router_w; 0] fp16
__device__ float  g_hl [NSPLIT * M_TOK * 128];   // 32 MB  split-K partials
__device__ __half g_hh [(size_t)M_TOK * RNK];    //  1 MB  h fp16
__device__ float  g_wgt[2 * M_TOK];              // 64 KB  per-token top1/top2 weights
__device__ int    g_cnt[2][NEXP];                // bucket counts
__device__ int    g_list[2][NEXP * M_TOK];       //  1 MB  bucket token lists
__device__ int2   g_tbl[2][96];                  // tile table (expert, start)
__device__ int    g_nt[2];                       // tiles per pass

// ---------------- helpers ----------------------------------------------------
__device__ __forceinline__ uint32_t smem_u32(const void* p) {
    return (uint32_t)__cvta_generic_to_shared(p);
}
__device__ __forceinline__ uint32_t pack2h(__half a, __half b) {
    return (uint32_t)__half_as_ushort(a) | ((uint32_t)__half_as_ushort(b) << 16);
}
__device__ __forceinline__ uint2 cvt4(float4 v) {
    return make_uint2(pack2h(__float2half_rn(v.x), __float2half_rn(v.y)),
                      pack2h(__float2half_rn(v.z), __float2half_rn(v.w)));
}

// ---------------- conversion kernels ------------------------------------------
#define NX      (M_TOK * DIN / 4)           // 8388608
#define NW2     (128 * DIN / 4)             // 131072
#define NXW2    (NX + NW2)                  // 8519680 = 33280 * 256
#define NWBASE  (DOUT * DIN / 4)            // 4194304
#define NB      (NEXP * DOUT * RNK / 4)     // 1048576
#define NWALL   (NWBASE + NB)               // 5242880 = 20480 * 256

__global__ void prep_xw2_kernel(const float4* __restrict__ x4,
                                const float* __restrict__ Am,
                                const float* __restrict__ rw)
{
    int i = blockIdx.x * blockDim.x + threadIdx.x;
    if (i < 32) ((int*)g_cnt)[i] = 0;                  // reset bucket counts
    if (i < NX) {
        float4 v = x4[i];
        *(uint2*)(g_x + ((size_t)i << 2)) = cvt4(v);
    } else {
        int j = i - NX;
        int e = j << 2;
        int r = e >> 12, k = e & (DIN - 1);
        float4 v = make_float4(0.f, 0.f, 0.f, 0.f);
        if (r < 64)      v = *(const float4*)(Am + (size_t)r * DIN + k);
        else if (r < 80) v = *(const float4*)(rw + (size_t)(r - 64) * DIN + k);
        *(uint2*)(g_w2 + (size_t)r * DIN + k) = cvt4(v);
    }
}

__global__ void prep_w_kernel(const float* __restrict__ bw,
                              const float* __restrict__ Bm)
{
    int j = blockIdx.x * blockDim.x + threadIdx.x;     // < NWALL
    if (j < NWBASE) {
        float4 v = *(const float4*)(bw + ((size_t)j << 2));
        *(uint2*)(g_w + ((size_t)j << 2)) = cvt4(v);
    } else {
        int q = j - NWBASE;                            // B is linear [e][o][r]
        float4 v = *(const float4*)(Bm + ((size_t)q << 2));
        *(uint2*)(g_wb + ((size_t)q << 2)) = cvt4(v);
    }
}

// ---------------- router: softmax/top2 -> h, weights, buckets -----------------
__global__ void router_kernel() {
    int warp = threadIdx.x >> 5, lane = threadIdx.x & 31;
    int t = blockIdx.x * 8 + warp;
    __shared__ float wsel[8][16];
    __shared__ float hsum[8][64];
    const float* p0 = g_hl + (size_t)t * 128;

    if (lane < 16) {
        float lg = 0.f;
        #pragma unroll
        for (int s = 0; s < NSPLIT; s++) lg += p0[(size_t)s * M_TOK * 128 + 64 + lane];
        wsel[warp][lane] = lg;
    }
    #pragma unroll
    for (int c = lane; c < 64; c += 32) {
        float hv = 0.f;
        #pragma unroll
        for (int s = 0; s < NSPLIT; s++) hv += p0[(size_t)s * M_TOK * 128 + c];
        hsum[warp][c] = hv;
    }
    __syncwarp();
    if (lane == 0) {
        float lg[16]; float m = -1e30f;
        #pragma unroll
        for (int e = 0; e < 16; e++) { lg[e] = wsel[warp][e]; m = fmaxf(m, lg[e]); }
        float p[16], Z = 0.f;
        #pragma unroll
        for (int e = 0; e < 16; e++) { p[e] = expf(lg[e] - m); Z += p[e]; }
        float inv = 1.f / Z;
        int i1 = 0; float b1 = -1.f;
        #pragma unroll
        for (int e = 0; e < 16; e++) if (p[e] > b1) { b1 = p[e]; i1 = e; }
        int i2 = 0; float b2 = -1.f;
        #pragma unroll
        for (int e = 0; e < 16; e++) if (e != i1 && p[e] > b2) { b2 = p[e]; i2 = e; }
        b1 *= inv; b2 *= inv;
        float den = b1 + b2 + 1e-6f;
        g_wgt[2 * t]     = (b1 / den) * SCALING;
        g_wgt[2 * t + 1] = (b2 / den) * SCALING;
        int pos0 = atomicAdd(&g_cnt[0][i1], 1);
        g_list[0][i1 * M_TOK + pos0] = t;
        int pos1 = atomicAdd(&g_cnt[1][i2], 1);
        g_list[1][i2 * M_TOK + pos1] = t;
    }
    __syncwarp();
    #pragma unroll
    for (int c = lane; c < 64; c += 32)
        g_hh[(size_t)t * RNK + c] = __float2half_rn(hsum[warp][c]);
}

// ---------------- tile table build --------------------------------------------
__global__ void build_tiles_kernel() {
    int p = threadIdx.x;
    if (p >= 2) return;
    int n = 0;
    for (int e = 0; e < NEXP; e++) {
        int c = g_cnt[p][e];
        for (int s = 0; s < c; s += 128) g_tbl[p][n++] = make_int2(e, s);
    }
    g_nt[p] = n;
}

// ---------------- common GEMM macros ------------------------------------------
#define CPASYNC(dst, src) \
    asm volatile("cp.async.cg.shared.global [%0], [%1], 16;\n" :: "r"(dst), "l"(src))
#define LDSM4(d, addr) \
    asm volatile("ldmatrix.sync.aligned.m8n8.x4.shared.b16 {%0,%1,%2,%3}, [%4];" \
        : "=r"((d)[0]), "=r"((d)[1]), "=r"((d)[2]), "=r"((d)[3]) : "r"(addr))
#define MMA16816(c, a, b) \
    asm volatile("mma.sync.aligned.m16n8k16.row.col.f32.f16.f16.f32 " \
        "{%0,%1,%2,%3}, {%4,%5,%6,%7}, {%8,%9}, {%0,%1,%2,%3};" \
        : "+f"((c)[0]), "+f"((c)[1]), "+f"((c)[2]), "+f"((c)[3]) \
        : "r"((a)[0]), "r"((a)[1]), "r"((a)[2]), "r"((a)[3]), "r"((b)[0]), "r"((b)[1]))

extern __shared__ __align__(128) unsigned char smem_buf[];

// ---------------- small GEMM: 128x128 tile, K32 chunks (split-K 8) ------------
#define LDT1     40
#define TILEH1   (128 * LDT1)
#define STAGEH1  (2 * TILEH1)
#define SMEM1    (3 * STAGEH1 * 2)          // 61440

__global__ __launch_bounds__(256, 2)
void gemm128_kernel(const __half* __restrict__ A, int lda,
                    const __half* __restrict__ B, int ldb,
                    float* __restrict__ C, int ldc, int Kdim)
{
    const int tid = threadIdx.x, lane = tid & 31, warp = tid >> 5;
    const int wm = warp >> 2, wn = warp & 3;
    const int bm = blockIdx.y << 7;
    const uint32_t smbase = smem_u32(smem_buf);

    const int koff = blockIdx.z * Kdim;
    A += koff; B += koff;
    C += (size_t)blockIdx.z * M_TOK * ldc;

    const int r0 = tid >> 2, q0 = (tid & 3) << 3, r1 = r0 + 64;
    const uint32_t ob0 = (uint32_t)(r0 * LDT1 + q0) * 2;
    const uint32_t ob1 = (uint32_t)(r1 * LDT1 + q0) * 2;

    const __half* gA0 = A + (size_t)(bm + r0) * lda + q0;
    const __half* gA1 = A + (size_t)(bm + r1) * lda + q0;
    const __half* gB0 = B + (size_t)r0 * ldb + q0;
    const __half* gB1 = B + (size_t)r1 * ldb + q0;

    auto issue_stage = [&](int st, int k0) {
        uint32_t sb = smbase + (uint32_t)st * (STAGEH1 * 2);
        CPASYNC(sb + ob0, gA0 + k0);
        CPASYNC(sb + ob1, gA1 + k0);
        CPASYNC(sb + TILEH1 * 2 + ob0, gB0 + k0);
        CPASYNC(sb + TILEH1 * 2 + ob1, gB1 + k0);
        asm volatile("cp.async.commit_group;\n" ::);
    };

    const uint32_t aBase = (uint32_t)((wm * 64 + (lane & 15)) * LDT1 + ((lane >> 4) << 3));
    const uint32_t bBase = (uint32_t)((wn * 32 + ((lane >> 4) << 3) + (lane & 7)) * LDT1
                                      + (((lane >> 3) & 1) << 3));
    float acc[4][4][4] = {};
    const int nk = Kdim >> 5;

    issue_stage(0, 0);
    if (nk > 1) issue_stage(1, 32);

    for (int kt = 0; kt < nk; kt++) {
        if (kt + 1 < nk) {
            asm volatile("cp.async.wait_group 1;\n" ::: "memory");
        } else {
            asm volatile("cp.async.wait_group 0;\n" ::: "memory");
        }
        __syncthreads();
        if (kt + 2 < nk) issue_stage((kt + 2) % 3, (kt + 2) << 5);

        uint32_t sb = smbase + (uint32_t)(kt % 3) * (STAGEH1 * 2);
        #pragma unroll
        for (int kk = 0; kk < 32; kk += 16) {
            uint32_t a[4][4], b[4][2];
            #pragma unroll
            for (int mi = 0; mi < 4; mi++)
                LDSM4(a[mi], sb + (aBase + mi * (16 * LDT1) + kk) * 2);
            #pragma unroll
            for (int h = 0; h < 2; h++) {
                uint32_t t4[4];
                LDSM4(t4, sb + TILEH1 * 2 + (bBase + h * (16 * LDT1) + kk) * 2);
                b[2*h][0] = t4[0]; b[2*h][1] = t4[1];
                b[2*h+1][0] = t4[2]; b[2*h+1][1] = t4[3];
            }
            #pragma unroll
            for (int mi = 0; mi < 4; mi++)
                #pragma unroll
                for (int nj = 0; nj < 4; nj++)
                    MMA16816(acc[mi][nj], a[mi], b[nj]);
        }
    }

    const int tr = lane >> 2, tc2 = (lane & 3) << 1;
    #pragma unroll
    for (int mi = 0; mi < 4; mi++) {
        int row = bm + wm * 64 + mi * 16 + tr;
        #pragma unroll
        for (int nj = 0; nj < 4; nj++) {
            int col = wn * 32 + nj * 8 + tc2;
            *(float2*)(C + (size_t)row * ldc + col) = make_float2(acc[mi][nj][0], acc[mi][nj][1]);
            *(float2*)(C + (size_t)(row + 8) * ldc + col) = make_float2(acc[mi][nj][2], acc[mi][nj][3]);
        }
    }
}

// ---------------- delta GEMM: expert-grouped 128x128xK64 ----------------------
#define LDTD     72
#define HB_OFF   18432                      // 128*72*2
#define IDS_OFF  36864
#define SMEMD    (IDS_OFF + 512 + 128)

__global__ __launch_bounds__(256, 2)
void delta_kernel(float* __restrict__ out, int pass)
{
    const int tid = threadIdx.x, lane = tid & 31, warp = tid >> 5;
    const int wm = warp >> 2, wn = warp & 3;
    if ((int)blockIdx.y >= g_nt[pass]) return;
    int2 te = g_tbl[pass][blockIdx.y];
    const int e = te.x, base = te.y;
    const int cnt = g_cnt[pass][e];
    const int n0 = blockIdx.x << 7;
    const uint32_t smb = smem_u32(smem_buf);
    int* ids = (int*)(smem_buf + IDS_OFF);

    if (tid < 128) {
        int i = base + tid;
        ids[tid] = (i < cnt) ? g_list[pass][e * M_TOK + i] : -1;
    }
    __syncthreads();

    // load scaled h rows and B_e tile into smem
    {
        int r = tid >> 1, hp = (tid & 1) << 5;          // 2 threads/row, 32 halves each
        int tok = ids[r];
        float w = (tok >= 0) ? g_wgt[2 * tok + pass] : 0.f;
        const __half* hrow = g_hh + (size_t)(tok >= 0 ? tok : 0) * RNK + hp;
        __half* dsth = (__half*)smem_buf + r * LDTD + hp;
        #pragma unroll
        for (int j = 0; j < 32; j++)
            dsth[j] = __float2half_rn(w * __half2float(hrow[j]));
        const __half* brow = g_wb + ((size_t)e * DOUT + (n0 + r)) * RNK + hp;
        __half* dstb = (__half*)(smem_buf + HB_OFF) + r * LDTD + hp;
        #pragma unroll
        for (int j = 0; j < 4; j++)
            *(uint4*)(dstb + j * 8) = *(const uint4*)(brow + j * 8);
    }
    __syncthreads();

    const uint32_t aBase = (uint32_t)((wm * 64 + (lane & 15)) * LDTD + ((lane >> 4) << 3));
    const uint32_t bBase = (uint32_t)((wn * 32 + ((lane >> 4) << 3) + (lane & 7)) * LDTD
                                      + (((lane >> 3) & 1) << 3));
    float acc[4][4][4] = {};
    #pragma unroll
    for (int kk = 0; kk < 64; kk += 16) {
        uint32_t a[4][4], b[4][2];
        #pragma unroll
        for (int mi = 0; mi < 4; mi++)
            LDSM4(a[mi], smb + (aBase + mi * (16 * LDTD) + kk) * 2);
        #pragma unroll
        for (int h = 0; h < 2; h++) {
            uint32_t t4[4];
            LDSM4(t4, smb + HB_OFF + (bBase + h * (16 * LDTD) + kk) * 2);
            b[2*h][0] = t4[0]; b[2*h][1] = t4[1];
            b[2*h+1][0] = t4[2]; b[2*h+1][1] = t4[3];
        }
        #pragma unroll
        for (int mi = 0; mi < 4; mi++)
            #pragma unroll
            for (int nj = 0; nj < 4; nj++)
                MMA16816(acc[mi][nj], a[mi], b[nj]);
    }

    const int tr = lane >> 2, tc2 = (lane & 3) << 1;
    #pragma unroll
    for (int mi = 0; mi < 4; mi++) {
        int r0 = wm * 64 + mi * 16 + tr;
        int tok0 = ids[r0], tok1 = ids[r0 + 8];
        #pragma unroll
        for (int nj = 0; nj < 4; nj++) {
            int col = n0 + wn * 32 + nj * 8 + tc2;
            if (tok0 >= 0) {
                float* p = out + (size_t)tok0 * DOUT + col;
                if (pass == 0) *(float2*)p = make_float2(acc[mi][nj][0], acc[mi][nj][1]);
                else { float2 o = *(float2*)p;
                       *(float2*)p = make_float2(o.x + acc[mi][nj][0], o.y + acc[mi][nj][1]); }
            }
            if (tok1 >= 0) {
                float* p = out + (size_t)tok1 * DOUT + col;
                if (pass == 0) *(float2*)p = make_float2(acc[mi][nj][2], acc[mi][nj][3]);
                else { float2 o = *(float2*)p;
                       *(float2*)p = make_float2(o.x + acc[mi][nj][2], o.y + acc[mi][nj][3]); }
            }
        }
    }
}

// ---------------- main GEMM: 128x128 block, K64 chunks, RMW epilogue ----------
#define LDT2     72
#define TILEH2   (128 * LDT2)
#define STAGE2B  (2 * TILEH2 * 2)           // 36864 B per stage
#define SMEM2    (3 * STAGE2B)              // 110592 B (2 CTAs/SM)

__global__ __launch_bounds__(256, 2)
void gemm_main_kernel(const __half* __restrict__ A,
                      const __half* __restrict__ B,
                      float* __restrict__ C,
                      const float* __restrict__ bias)
{
    const int tid = threadIdx.x, lane = tid & 31, warp = tid >> 5;
    const int wm = warp >> 2, wn = warp & 3;
    const int bm = blockIdx.y << 7, bn = blockIdx.x << 7;
    const uint32_t smbase = smem_u32(smem_buf);

    uint32_t aob[4];
    const __half *gA[4], *gB[4];
    #pragma unroll
    for (int j = 0; j < 4; j++) {
        int c = tid + 256 * j;
        int row = c >> 3, q = (c & 7) << 3;
        aob[j] = (uint32_t)(row * LDT2 + q) * 2;
        gA[j] = A + (size_t)(bm + row) * DIN + q;
        gB[j] = B + (size_t)(bn + row) * DIN + q;
    }

    auto issue_stage = [&](int st, int k0) {
        uint32_t sb = smbase + (uint32_t)st * STAGE2B;
        #pragma unroll
        for (int j = 0; j < 4; j++) CPASYNC(sb + aob[j], gA[j] + k0);
        uint32_t sb2 = sb + TILEH2 * 2;
        #pragma unroll
        for (int j = 0; j < 4; j++) CPASYNC(sb2 + aob[j], gB[j] + k0);
        asm volatile("cp.async.commit_group;\n" ::);
    };

    const uint32_t aBase = (uint32_t)((wm * 64 + (lane & 15)) * LDT2 + ((lane >> 4) << 3));
    const uint32_t bBase = (uint32_t)((wn * 32 + ((lane >> 4) << 3) + (lane & 7)) * LDT2
                                      + (((lane >> 3) & 1) << 3));
    float acc[4][4][4] = {};
    const int nk = DIN >> 6;                            // 64

    issue_stage(0, 0);
    issue_stage(1, 64);

    for (int kt = 0; kt < nk; kt++) {
        if (kt + 1 < nk) {
            asm volatile("cp.async.wait_group 1;\n" ::: "memory");
        } else {
            asm volatile("cp.async.wait_group 0;\n" ::: "memory");
        }
        __syncthreads();
        if (kt + 2 < nk) issue_stage((kt + 2) % 3, (kt + 2) << 6);

        uint32_t sb = smbase + (uint32_t)(kt % 3) * STAGE2B;
        #pragma unroll
        for (int kk = 0; kk < 64; kk += 16) {
            uint32_t a[4][4], b[4][2];
            #pragma unroll
            for (int mi = 0; mi < 4; mi++)
                LDSM4(a[mi], sb + (aBase + mi * (16 * LDT2) + kk) * 2);
            #pragma unroll
            for (int h = 0; h < 2; h++) {
                uint32_t t4[4];
                LDSM4(t4, sb + TILEH2 * 2 + (bBase + h * (16 * LDT2) + kk) * 2);
                b[2*h][0] = t4[0]; b[2*h][1] = t4[1];
                b[2*h+1][0] = t4[2]; b[2*h+1][1] = t4[3];
            }
            #pragma unroll
            for (int mi = 0; mi < 4; mi++)
                #pragma unroll
                for (int nj = 0; nj < 4; nj++)
                    MMA16816(acc[mi][nj], a[mi], b[nj]);
        }
    }

    // epilogue: out = delta(already in C) + x@W^T + bias
    const int tr = lane >> 2, tc2 = (lane & 3) << 1;
    #pragma unroll
    for (int mi = 0; mi < 4; mi++) {
        int row = bm + wm * 64 + mi * 16 + tr;
        #pragma unroll
        for (int nj = 0; nj < 4; nj++) {
            int col = bn + wn * 32 + nj * 8 + tc2;
            float b0 = bias[col], b1 = bias[col + 1];
            float* p0 = C + (size_t)row * DOUT + col;
            float* p1 = C + (size_t)(row + 8) * DOUT + col;
            float2 o0 = *(float2*)p0, o1 = *(float2*)p1;
            *(float2*)p0 = make_float2(o0.x + acc[mi][nj][0] + b0,
                                       o0.y + acc[mi][nj][1] + b1);
            *(float2*)p1 = make_float2(o1.x + acc[mi][nj][2] + b0,
                                       o1.y + acc[mi][nj][3] + b1);
        }
    }
}

// ---------------- launch ------------------------------------------------------
extern "C" void kernel_launch(void* const* d_in, const int* in_sizes, int n_in,
                              void* d_out, int out_size)
{
    const float* x  = (const float*)d_in[0];
    const float* bw = (const float*)d_in[1];
    const float* bb = (const float*)d_in[2];
    const float* Am = (const float*)d_in[3];
    const float* Bm = (const float*)d_in[4];
    const float* rw = (const float*)d_in[5];
    float* out = (float*)d_out;

    void *px, *pw, *pw2, *phl;
    cudaGetSymbolAddress(&px,  g_x);
    cudaGetSymbolAddress(&pw,  g_w);
    cudaGetSymbolAddress(&pw2, g_w2);
    cudaGetSymbolAddress(&phl, g_hl);

    cudaFuncSetAttribute(gemm128_kernel,
                         cudaFuncAttributeMaxDynamicSharedMemorySize, SMEM1);
    cudaFuncSetAttribute(delta_kernel,
                         cudaFuncAttributeMaxDynamicSharedMemorySize, SMEMD);
    cudaFuncSetAttribute(gemm_main_kernel,
                         cudaFuncAttributeMaxDynamicSharedMemorySize, SMEM2);

    prep_xw2_kernel<<<NXW2 / 256, 256>>>((const float4*)x, Am, rw);
    prep_w_kernel<<<NWALL / 256, 256>>>(bw, Bm);

    // hidden + router logits: [8192,128] = x @ w2^T, split-K 8
    gemm128_kernel<<<dim3(1, 64, NSPLIT), 256, SMEM1>>>(
        (const __half*)px, DIN,
        (const __half*)pw2, DIN,
        (float*)phl, 128, DIN / NSPLIT);

    router_kernel<<<M_TOK / 8, 256>>>();
    build_tiles_kernel<<<1, 32>>>();

    // expert-grouped delta: pass 0 writes out, pass 1 accumulates
    delta_kernel<<<dim3(DOUT / 128, 96), 256, SMEMD>>>(out, 0);
    delta_kernel<<<dim3(DOUT / 128, 96), 256, SMEMD>>>(out, 1);

    // dense base GEMM, K=4096, RMW epilogue adds bias + delta
    gemm_main_kernel<<<dim3(DOUT / 128, M_TOK / 128), 256, SMEM2>>>(
        (const __half*)px, (const __half*)pw, out, bb);
}

// round 16
// speedup vs baseline: 1.0319x; 1.0319x over previous
#include <cuda_runtime.h>
#include <cuda_fp16.h>
#include <cstdint>

#define M_TOK   8192
#define DIN     4096
#define DOUT    4096
#define RNK     64
#define NEXP    16
#define SCALING 0.5f
#define NSPLIT  8

// ---------------- scratch (static device globals; no allocations) -----------
__device__ __half g_x  [(size_t)M_TOK * DIN];       // 64 MB  x fp16 row-major
__device__ __half g_w  [(size_t)DOUT * DIN];        // 32 MB  base_w fp16
__device__ __half g_wb [(size_t)NEXP * DOUT * RNK]; //  8 MB  B fp16 [e][o][r]
__device__ __half g_w2 [128 * DIN];                 //  1 MB  [A; router_w; 0] fp16
__device__ float  g_hl [NSPLIT * M_TOK * 128];      // 32 MB  split-K partials
__device__ __half g_gh [2][(size_t)M_TOK * RNK];    //  2 MB  pre-scaled w*h per pass
__device__ int    g_cnt[2][NEXP];                   // bucket counts
__device__ int    g_list[2][NEXP * M_TOK];          //  1 MB  bucket token lists
__device__ int2   g_tbl[2][96];                     // tile table (expert, start)
__device__ int    g_nt[2];                          // tiles per pass

// ---------------- helpers ----------------------------------------------------
__device__ __forceinline__ uint32_t smem_u32(const void* p) {
    return (uint32_t)__cvta_generic_to_shared(p);
}
__device__ __forceinline__ uint32_t pack2h(__half a, __half b) {
    return (uint32_t)__half_as_ushort(a) | ((uint32_t)__half_as_ushort(b) << 16);
}
__device__ __forceinline__ uint2 cvt4(float4 v) {
    return make_uint2(pack2h(__float2half_rn(v.x), __float2half_rn(v.y)),
                      pack2h(__float2half_rn(v.z), __float2half_rn(v.w)));
}

// ---------------- conversion kernels ------------------------------------------
#define NX      (M_TOK * DIN / 4)           // 8388608
#define NW2     (128 * DIN / 4)             // 131072
#define NXW2    (NX + NW2)                  // 8519680 = 33280 * 256
#define NWBASE  (DOUT * DIN / 4)            // 4194304
#define NB      (NEXP * DOUT * RNK / 4)     // 1048576
#define NWALL   (NWBASE + NB)               // 5242880 = 20480 * 256

__global__ void prep_xw2_kernel(const float4* __restrict__ x4,
                                const float* __restrict__ Am,
                                const float* __restrict__ rw)
{
    int i = blockIdx.x * blockDim.x + threadIdx.x;
    if (i < 32) ((int*)g_cnt)[i] = 0;                  // reset bucket counts
    if (i < NX) {
        float4 v = x4[i];
        *(uint2*)(g_x + ((size_t)i << 2)) = cvt4(v);
    } else {
        int j = i - NX;
        int e = j << 2;
        int r = e >> 12, k = e & (DIN - 1);
        float4 v = make_float4(0.f, 0.f, 0.f, 0.f);
        if (r < 64)      v = *(const float4*)(Am + (size_t)r * DIN + k);
        else if (r < 80) v = *(const float4*)(rw + (size_t)(r - 64) * DIN + k);
        *(uint2*)(g_w2 + (size_t)r * DIN + k) = cvt4(v);
    }
}

__global__ void prep_w_kernel(const float* __restrict__ bw,
                              const float* __restrict__ Bm)
{
    int j = blockIdx.x * blockDim.x + threadIdx.x;     // < NWALL
    if (j < NWBASE) {
        float4 v = *(const float4*)(bw + ((size_t)j << 2));
        *(uint2*)(g_w + ((size_t)j << 2)) = cvt4(v);
    } else {
        int q = j - NWBASE;                            // B is linear [e][o][r]
        float4 v = *(const float4*)(Bm + ((size_t)q << 2));
        *(uint2*)(g_wb + ((size_t)q << 2)) = cvt4(v);
    }
}

// ---------------- router: softmax/top2 -> scaled h, buckets -------------------
__global__ void router_kernel() {
    int warp = threadIdx.x >> 5, lane = threadIdx.x & 31;
    int t = blockIdx.x * 8 + warp;
    __shared__ float wsel[8][16];
    __shared__ float hsum[8][64];
    const float* p0 = g_hl + (size_t)t * 128;

    if (lane < 16) {
        float lg = 0.f;
        #pragma unroll
        for (int s = 0; s < NSPLIT; s++) lg += p0[(size_t)s * M_TOK * 128 + 64 + lane];
        wsel[warp][lane] = lg;
    }
    #pragma unroll
    for (int c = lane; c < 64; c += 32) {
        float hv = 0.f;
        #pragma unroll
        for (int s = 0; s < NSPLIT; s++) hv += p0[(size_t)s * M_TOK * 128 + c];
        hsum[warp][c] = hv;
    }
    __syncwarp();
    if (lane == 0) {
        float lg[16]; float m = -1e30f;
        #pragma unroll
        for (int e = 0; e < 16; e++) { lg[e] = wsel[warp][e]; m = fmaxf(m, lg[e]); }
        float p[16], Z = 0.f;
        #pragma unroll
        for (int e = 0; e < 16; e++) { p[e] = expf(lg[e] - m); Z += p[e]; }
        float inv = 1.f / Z;
        int i1 = 0; float b1 = -1.f;
        #pragma unroll
        for (int e = 0; e < 16; e++) if (p[e] > b1) { b1 = p[e]; i1 = e; }
        int i2 = 0; float b2 = -1.f;
        #pragma unroll
        for (int e = 0; e < 16; e++) if (e != i1 && p[e] > b2) { b2 = p[e]; i2 = e; }
        b1 *= inv; b2 *= inv;
        float den = b1 + b2 + 1e-6f;
        wsel[warp][0] = (b1 / den) * SCALING;           // reuse smem for broadcast
        wsel[warp][1] = (b2 / den) * SCALING;
        int pos0 = atomicAdd(&g_cnt[0][i1], 1);
        g_list[0][i1 * M_TOK + pos0] = t;
        int pos1 = atomicAdd(&g_cnt[1][i2], 1);
        g_list[1][i2 * M_TOK + pos1] = t;
    }
    __syncwarp();
    float w0 = wsel[warp][0], w1 = wsel[warp][1];
    #pragma unroll
    for (int c = lane; c < 64; c += 32) {
        float hv = hsum[warp][c];
        g_gh[0][(size_t)t * RNK + c] = __float2half_rn(w0 * hv);
        g_gh[1][(size_t)t * RNK + c] = __float2half_rn(w1 * hv);
    }
}

// ---------------- tile table build --------------------------------------------
__global__ void build_tiles_kernel() {
    int p = threadIdx.x;
    if (p >= 2) return;
    int n = 0;
    for (int e = 0; e < NEXP; e++) {
        int c = g_cnt[p][e];
        for (int s = 0; s < c; s += 128) g_tbl[p][n++] = make_int2(e, s);
    }
    g_nt[p] = n;
}

// ---------------- common GEMM macros ------------------------------------------
#define CPASYNC(dst, src) \
    asm volatile("cp.async.cg.shared.global [%0], [%1], 16;\n" :: "r"(dst), "l"(src))
#define LDSM4(d, addr) \
    asm volatile("ldmatrix.sync.aligned.m8n8.x4.shared.b16 {%0,%1,%2,%3}, [%4];" \
        : "=r"((d)[0]), "=r"((d)[1]), "=r"((d)[2]), "=r"((d)[3]) : "r"(addr))
#define MMA16816(c, a, b) \
    asm volatile("mma.sync.aligned.m16n8k16.row.col.f32.f16.f16.f32 " \
        "{%0,%1,%2,%3}, {%4,%5,%6,%7}, {%8,%9}, {%0,%1,%2,%3};" \
        : "+f"((c)[0]), "+f"((c)[1]), "+f"((c)[2]), "+f"((c)[3]) \
        : "r"((a)[0]), "r"((a)[1]), "r"((a)[2]), "r"((a)[3]), "r"((b)[0]), "r"((b)[1]))

extern __shared__ __align__(128) unsigned char smem_buf[];

// ---------------- small GEMM: 128x128 tile, K32 chunks (split-K 8) ------------
#define LDT1     40
#define TILEH1   (128 * LDT1)
#define STAGEH1  (2 * TILEH1)
#define SMEM1    (3 * STAGEH1 * 2)          // 61440

__global__ __launch_bounds__(256, 2)
void gemm128_kernel(const __half* __restrict__ A, int lda,
                    const __half* __restrict__ B, int ldb,
                    float* __restrict__ C, int ldc, int Kdim)
{
    const int tid = threadIdx.x, lane = tid & 31, warp = tid >> 5;
    const int wm = warp >> 2, wn = warp & 3;
    const int bm = blockIdx.y << 7;
    const uint32_t smbase = smem_u32(smem_buf);

    const int koff = blockIdx.z * Kdim;
    A += koff; B += koff;
    C += (size_t)blockIdx.z * M_TOK * ldc;

    const int r0 = tid >> 2, q0 = (tid & 3) << 3, r1 = r0 + 64;
    const uint32_t ob0 = (uint32_t)(r0 * LDT1 + q0) * 2;
    const uint32_t ob1 = (uint32_t)(r1 * LDT1 + q0) * 2;

    const __half* gA0 = A + (size_t)(bm + r0) * lda + q0;
    const __half* gA1 = A + (size_t)(bm + r1) * lda + q0;
    const __half* gB0 = B + (size_t)r0 * ldb + q0;
    const __half* gB1 = B + (size_t)r1 * ldb + q0;

    auto issue_stage = [&](int st, int k0) {
        uint32_t sb = smbase + (uint32_t)st * (STAGEH1 * 2);
        CPASYNC(sb + ob0, gA0 + k0);
        CPASYNC(sb + ob1, gA1 + k0);
        CPASYNC(sb + TILEH1 * 2 + ob0, gB0 + k0);
        CPASYNC(sb + TILEH1 * 2 + ob1, gB1 + k0);
        asm volatile("cp.async.commit_group;\n" ::);
    };

    const uint32_t aBase = (uint32_t)((wm * 64 + (lane & 15)) * LDT1 + ((lane >> 4) << 3));
    const uint32_t bBase = (uint32_t)((wn * 32 + ((lane >> 4) << 3) + (lane & 7)) * LDT1
                                      + (((lane >> 3) & 1) << 3));
    float acc[4][4][4] = {};
    const int nk = Kdim >> 5;

    issue_stage(0, 0);
    if (nk > 1) issue_stage(1, 32);

    for (int kt = 0; kt < nk; kt++) {
        if (kt + 1 < nk) {
            asm volatile("cp.async.wait_group 1;\n" ::: "memory");
        } else {
            asm volatile("cp.async.wait_group 0;\n" ::: "memory");
        }
        __syncthreads();
        if (kt + 2 < nk) issue_stage((kt + 2) % 3, (kt + 2) << 5);

        uint32_t sb = smbase + (uint32_t)(kt % 3) * (STAGEH1 * 2);
        #pragma unroll
        for (int kk = 0; kk < 32; kk += 16) {
            uint32_t a[4][4], b[4][2];
            #pragma unroll
            for (int mi = 0; mi < 4; mi++)
                LDSM4(a[mi], sb + (aBase + mi * (16 * LDT1) + kk) * 2);
            #pragma unroll
            for (int h = 0; h < 2; h++) {
                uint32_t t4[4];
                LDSM4(t4, sb + TILEH1 * 2 + (bBase + h * (16 * LDT1) + kk) * 2);
                b[2*h][0] = t4[0]; b[2*h][1] = t4[1];
                b[2*h+1][0] = t4[2]; b[2*h+1][1] = t4[3];
            }
            #pragma unroll
            for (int mi = 0; mi < 4; mi++)
                #pragma unroll
                for (int nj = 0; nj < 4; nj++)
                    MMA16816(acc[mi][nj], a[mi], b[nj]);
        }
    }

    const int tr = lane >> 2, tc2 = (lane & 3) << 1;
    #pragma unroll
    for (int mi = 0; mi < 4; mi++) {
        int row = bm + wm * 64 + mi * 16 + tr;
        #pragma unroll
        for (int nj = 0; nj < 4; nj++) {
            int col = wn * 32 + nj * 8 + tc2;
            *(float2*)(C + (size_t)row * ldc + col) = make_float2(acc[mi][nj][0], acc[mi][nj][1]);
            *(float2*)(C + (size_t)(row + 8) * ldc + col) = make_float2(acc[mi][nj][2], acc[mi][nj][3]);
        }
    }
}

// ---------------- delta GEMM: expert-grouped 128x128xK64, cp.async fill -------
#define LDTD     72
#define HB_OFF   (128 * LDTD * 2)           // 18432
#define IDS_OFF  (2 * HB_OFF)               // 36864
#define SMEMD    (IDS_OFF + 640)

__global__ __launch_bounds__(256, 2)
void delta_kernel(float* __restrict__ out, const __half* __restrict__ gh, int pass)
{
    const int tid = threadIdx.x, lane = tid & 31, warp = tid >> 5;
    const int wm = warp >> 2, wn = warp & 3;
    if ((int)blockIdx.y >= g_nt[pass]) return;
    int2 te = g_tbl[pass][blockIdx.y];
    const int e = te.x, base = te.y;
    const int cnt = g_cnt[pass][e];
    const int n0 = blockIdx.x << 7;
    const uint32_t smb = smem_u32(smem_buf);
    int* ids = (int*)(smem_buf + IDS_OFF);

    if (tid < 128) {
        int i = base + tid;
        ids[tid] = (i < cnt) ? g_list[pass][e * M_TOK + i] : -1;
    }
    __syncthreads();

    // cp.async fill: h tile (gathered, pre-scaled) + B_e tile, 16B chunks
    const __half* bbase = g_wb + ((size_t)e * DOUT + n0) * RNK;
    #pragma unroll
    for (int it = 0; it < 4; it++) {
        int c = tid + 256 * it;                     // 0..1023
        int r = c >> 3, q = (c & 7) << 3;           // row, half-offset
        int tok = ids[r]; if (tok < 0) tok = 0;     // clamp: garbage rows guarded below
        CPASYNC(smb + (uint32_t)(r * LDTD + q) * 2, gh + (size_t)tok * RNK + q);
        CPASYNC(smb + HB_OFF + (uint32_t)(r * LDTD + q) * 2, bbase + (size_t)r * RNK + q);
    }
    asm volatile("cp.async.commit_group;\n" ::);
    asm volatile("cp.async.wait_group 0;\n" ::: "memory");
    __syncthreads();

    const uint32_t aBase = (uint32_t)((wm * 64 + (lane & 15)) * LDTD + ((lane >> 4) << 3));
    const uint32_t bBase = (uint32_t)((wn * 32 + ((lane >> 4) << 3) + (lane & 7)) * LDTD
                                      + (((lane >> 3) & 1) << 3));
    float acc[4][4][4] = {};
    #pragma unroll
    for (int kk = 0; kk < 64; kk += 16) {
        uint32_t a[4][4], b[4][2];
        #pragma unroll
        for (int mi = 0; mi < 4; mi++)
            LDSM4(a[mi], smb + (aBase + mi * (16 * LDTD) + kk) * 2);
        #pragma unroll
        for (int h = 0; h < 2; h++) {
            uint32_t t4[4];
            LDSM4(t4, smb + HB_OFF + (bBase + h * (16 * LDTD) + kk) * 2);
            b[2*h][0] = t4[0]; b[2*h][1] = t4[1];
            b[2*h+1][0] = t4[2]; b[2*h+1][1] = t4[3];
        }
        #pragma unroll
        for (int mi = 0; mi < 4; mi++)
            #pragma unroll
            for (int nj = 0; nj < 4; nj++)
                MMA16816(acc[mi][nj], a[mi], b[nj]);
    }

    const int tr = lane >> 2, tc2 = (lane & 3) << 1;
    #pragma unroll
    for (int mi = 0; mi < 4; mi++) {
        int r0 = wm * 64 + mi * 16 + tr;
        int tok0 = ids[r0], tok1 = ids[r0 + 8];
        #pragma unroll
        for (int nj = 0; nj < 4; nj++) {
            int col = n0 + wn * 32 + nj * 8 + tc2;
            if (tok0 >= 0) {
                float* p = out + (size_t)tok0 * DOUT + col;
                if (pass == 0) *(float2*)p = make_float2(acc[mi][nj][0], acc[mi][nj][1]);
                else { float2 o = *(float2*)p;
                       *(float2*)p = make_float2(o.x + acc[mi][nj][0], o.y + acc[mi][nj][1]); }
            }
            if (tok1 >= 0) {
                float* p = out + (size_t)tok1 * DOUT + col;
                if (pass == 0) *(float2*)p = make_float2(acc[mi][nj][2], acc[mi][nj][3]);
                else { float2 o = *(float2*)p;
                       *(float2*)p = make_float2(o.x + acc[mi][nj][2], o.y + acc[mi][nj][3]); }
            }
        }
    }
}

// ---------------- main GEMM: 128x128 block, K64 chunks, RMW epilogue ----------
#define LDT2     72
#define TILEH2   (128 * LDT2)
#define STAGE2B  (2 * TILEH2 * 2)           // 36864 B per stage
#define SMEM2    (3 * STAGE2B)              // 110592 B (2 CTAs/SM)

__global__ __launch_bounds__(256, 2)
void gemm_main_kernel(const __half* __restrict__ A,
                      const __half* __restrict__ B,
                      float* __restrict__ C,
                      const float* __restrict__ bias)
{
    const int tid = threadIdx.x, lane = tid & 31, warp = tid >> 5;
    const int wm = warp >> 2, wn = warp & 3;
    const int bm = blockIdx.y << 7, bn = blockIdx.x << 7;
    const uint32_t smbase = smem_u32(smem_buf);

    uint32_t aob[4];
    const __half *gA[4], *gB[4];
    #pragma unroll
    for (int j = 0; j < 4; j++) {
        int c = tid + 256 * j;
        int row = c >> 3, q = (c & 7) << 3;
        aob[j] = (uint32_t)(row * LDT2 + q) * 2;
        gA[j] = A + (size_t)(bm + row) * DIN + q;
        gB[j] = B + (size_t)(bn + row) * DIN + q;
    }

    auto issue_stage = [&](int st, int k0) {
        uint32_t sb = smbase + (uint32_t)st * STAGE2B;
        #pragma unroll
        for (int j = 0; j < 4; j++) CPASYNC(sb + aob[j], gA[j] + k0);
        uint32_t sb2 = sb + TILEH2 * 2;
        #pragma unroll
        for (int j = 0; j < 4; j++) CPASYNC(sb2 + aob[j], gB[j] + k0);
        asm volatile("cp.async.commit_group;\n" ::);
    };

    const uint32_t aBase = (uint32_t)((wm * 64 + (lane & 15)) * LDT2 + ((lane >> 4) << 3));
    const uint32_t bBase = (uint32_t)((wn * 32 + ((lane >> 4) << 3) + (lane & 7)) * LDT2
                                      + (((lane >> 3) & 1) << 3));
    float acc[4][4][4] = {};
    const int nk = DIN >> 6;                            // 64

    issue_stage(0, 0);
    issue_stage(1, 64);

    for (int kt = 0; kt < nk; kt++) {
        if (kt + 1 < nk) {
            asm volatile("cp.async.wait_group 1;\n" ::: "memory");
        } else {
            asm volatile("cp.async.wait_group 0;\n" ::: "memory");
        }
        __syncthreads();
        if (kt + 2 < nk) issue_stage((kt + 2) % 3, (kt + 2) << 6);

        uint32_t sb = smbase + (uint32_t)(kt % 3) * STAGE2B;
        #pragma unroll
        for (int kk = 0; kk < 64; kk += 16) {
            uint32_t a[4][4], b[4][2];
            #pragma unroll
            for (int mi = 0; mi < 4; mi++)
                LDSM4(a[mi], sb + (aBase + mi * (16 * LDT2) + kk) * 2);
            #pragma unroll
            for (int h = 0; h < 2; h++) {
                uint32_t t4[4];
                LDSM4(t4, sb + TILEH2 * 2 + (bBase + h * (16 * LDT2) + kk) * 2);
                b[2*h][0] = t4[0]; b[2*h][1] = t4[1];
                b[2*h+1][0] = t4[2]; b[2*h+1][1] = t4[3];
            }
            #pragma unroll
            for (int mi = 0; mi < 4; mi++)
                #pragma unroll
                for (int nj = 0; nj < 4; nj++)
                    MMA16816(acc[mi][nj], a[mi], b[nj]);
        }
    }

    // epilogue: out = delta(already in C) + x@W^T + bias
    const int tr = lane >> 2, tc2 = (lane & 3) << 1;
    #pragma unroll
    for (int mi = 0; mi < 4; mi++) {
        int row = bm + wm * 64 + mi * 16 + tr;
        #pragma unroll
        for (int nj = 0; nj < 4; nj++) {
            int col = bn + wn * 32 + nj * 8 + tc2;
            float b0 = bias[col], b1 = bias[col + 1];
            float* p0 = C + (size_t)row * DOUT + col;
            float* p1 = C + (size_t)(row + 8) * DOUT + col;
            float2 o0 = *(float2*)p0, o1 = *(float2*)p1;
            *(float2*)p0 = make_float2(o0.x + acc[mi][nj][0] + b0,
                                       o0.y + acc[mi][nj][1] + b1);
            *(float2*)p1 = make_float2(o1.x + acc[mi][nj][2] + b0,
                                       o1.y + acc[mi][nj][3] + b1);
        }
    }
}

// ---------------- launch ------------------------------------------------------
extern "C" void kernel_launch(void* const* d_in, const int* in_sizes, int n_in,
                              void* d_out, int out_size)
{
    const float* x  = (const float*)d_in[0];
    const float* bw = (const float*)d_in[1];
    const float* bb = (const float*)d_in[2];
    const float* Am = (const float*)d_in[3];
    const float* Bm = (const float*)d_in[4];
    const float* rw = (const float*)d_in[5];
    float* out = (float*)d_out;

    void *px, *pw, *pw2, *phl, *pgh;
    cudaGetSymbolAddress(&px,  g_x);
    cudaGetSymbolAddress(&pw,  g_w);
    cudaGetSymbolAddress(&pw2, g_w2);
    cudaGetSymbolAddress(&phl, g_hl);
    cudaGetSymbolAddress(&pgh, g_gh);

    cudaFuncSetAttribute(gemm128_kernel,
                         cudaFuncAttributeMaxDynamicSharedMemorySize, SMEM1);
    cudaFuncSetAttribute(delta_kernel,
                         cudaFuncAttributeMaxDynamicSharedMemorySize, SMEMD);
    cudaFuncSetAttribute(gemm_main_kernel,
                         cudaFuncAttributeMaxDynamicSharedMemorySize, SMEM2);

    prep_xw2_kernel<<<NXW2 / 256, 256>>>((const float4*)x, Am, rw);
    prep_w_kernel<<<NWALL / 256, 256>>>(bw, Bm);

    // hidden + router logits: [8192,128] = x @ w2^T, split-K 8
    gemm128_kernel<<<dim3(1, 64, NSPLIT), 256, SMEM1>>>(
        (const __half*)px, DIN,
        (const __half*)pw2, DIN,
        (float*)phl, 128, DIN / NSPLIT);

    router_kernel<<<M_TOK / 8, 256>>>();
    build_tiles_kernel<<<1, 32>>>();

    // expert-grouped delta: pass 0 writes out, pass 1 accumulates
    const __half* gh0 = (const __half*)pgh;
    const __half* gh1 = (const __half*)pgh + (size_t)M_TOK * RNK;
    delta_kernel<<<dim3(DOUT / 128, 96), 256, SMEMD>>>(out, gh0, 0);
    delta_kernel<<<dim3(DOUT / 128, 96), 256, SMEMD>>>(out, gh1, 1);

    // dense base GEMM, K=4096, RMW epilogue adds bias + delta
    gemm_main_kernel<<<dim3(DOUT / 128, M_TOK / 128), 256, SMEM2>>>(
        (const __half*)px, (const __half*)pw, out, bb);
}

// round 17
// speedup vs baseline: 1.1745x; 1.1382x over previous
#include <cuda_runtime.h>
#include <cuda_fp16.h>
#include <cstdint>

#define M_TOK   8192
#define DIN     4096
#define DOUT    4096
#define RNK     64
#define NEXP    16
#define KG      1024
#define KTOT    5120
#define SCALING 0.5f
#define NSPLIT  8

// ---------------- scratch (static device globals; no allocations) -----------
__device__ __half g_xg[(size_t)M_TOK * KTOT];   // 80 MB  [x | g] fp16, row-major
__device__ __half g_wt[(size_t)DOUT * KTOT];    // 40 MB  [base_w | B_flat] fp16
__device__ __half g_w2[128 * DIN];              //  1 MB  [A; router_w; 0] fp16
__device__ float  g_hl[NSPLIT * M_TOK * 128];   // 32 MB  split-K partials
__device__ int    g_e12[M_TOK];                 // per-token packed (e1 | e2<<8)
__device__ int    g_pcnt[256];                  // pair-bucket counts -> offsets
__device__ int    g_order[M_TOK];               // tokens sorted by expert pair
__device__ int    g_chunks[64][80];             // per-M-tile K-chunk list
__device__ int    g_nchunks[64];

// ---------------- helpers ----------------------------------------------------
__device__ __forceinline__ uint32_t smem_u32(const void* p) {
    return (uint32_t)__cvta_generic_to_shared(p);
}
__device__ __forceinline__ uint32_t pack2h(__half a, __half b) {
    return (uint32_t)__half_as_ushort(a) | ((uint32_t)__half_as_ushort(b) << 16);
}
__device__ __forceinline__ uint2 cvt4(float4 v) {
    return make_uint2(pack2h(__float2half_rn(v.x), __float2half_rn(v.y)),
                      pack2h(__float2half_rn(v.z), __float2half_rn(v.w)));
}

// ---------------- merged conversion kernel ------------------------------------
#define NX   (M_TOK * DIN / 4)              // 8388608
#define NW   (DOUT * KTOT / 4)              // 5242880
#define NW2  (128 * DIN / 4)                // 131072
#define NPREP (NX + NW + NW2)               // 13762560 = 53760 * 256

__global__ void prep_all_kernel(const float4* __restrict__ x4,
                                const float* __restrict__ bw,
                                const float* __restrict__ Bm,
                                const float* __restrict__ Am,
                                const float* __restrict__ rw)
{
    int i = blockIdx.x * blockDim.x + threadIdx.x;
    if (i < 256) g_pcnt[i] = 0;
    if (i < NX) {
        float4 v = x4[i];
        int e = i << 2;
        int row = e >> 12, col = e & (DIN - 1);
        *(uint2*)(g_xg + (size_t)row * KTOT + col) = cvt4(v);
    } else if (i < NX + NW) {
        int j = i - NX;
        int e = j << 2;
        int o = e / KTOT, k = e - o * KTOT;
        float4 v;
        if (k < DIN) {
            v = *(const float4*)(bw + (size_t)o * DIN + k);
        } else {
            int kk = k - DIN, ei = kk >> 6, r = kk & 63;
            v = *(const float4*)(Bm + ((size_t)(ei * DOUT + o) * RNK + r));
        }
        *(uint2*)(g_wt + (size_t)o * KTOT + k) = cvt4(v);
    } else {
        int j = i - NX - NW;
        int e = j << 2;
        int r = e >> 12, k = e & (DIN - 1);
        float4 v = make_float4(0.f, 0.f, 0.f, 0.f);
        if (r < 64)      v = *(const float4*)(Am + (size_t)r * DIN + k);
        else if (r < 80) v = *(const float4*)(rw + (size_t)(r - 64) * DIN + k);
        *(uint2*)(g_w2 + (size_t)r * DIN + k) = cvt4(v);
    }
}

// ---------------- router: softmax/top2 -> g columns + pair buckets ------------
__global__ void router_kernel() {
    int warp = threadIdx.x >> 5, lane = threadIdx.x & 31;
    int t = blockIdx.x * 8 + warp;
    __shared__ float wsel[8][16];
    __shared__ float hsum[8][64];
    const float* p0 = g_hl + (size_t)t * 128;

    if (lane < 16) {
        float lg = 0.f;
        #pragma unroll
        for (int s = 0; s < NSPLIT; s++) lg += p0[(size_t)s * M_TOK * 128 + 64 + lane];
        wsel[warp][lane] = lg;
    }
    #pragma unroll
    for (int c = lane; c < 64; c += 32) {
        float hv = 0.f;
        #pragma unroll
        for (int s = 0; s < NSPLIT; s++) hv += p0[(size_t)s * M_TOK * 128 + c];
        hsum[warp][c] = hv;
    }
    __syncwarp();
    if (lane == 0) {
        float lg[16]; float m = -1e30f;
        #pragma unroll
        for (int e = 0; e < 16; e++) { lg[e] = wsel[warp][e]; m = fmaxf(m, lg[e]); }
        float p[16], Z = 0.f;
        #pragma unroll
        for (int e = 0; e < 16; e++) { p[e] = expf(lg[e] - m); Z += p[e]; }
        float inv = 1.f / Z;
        int i1 = 0; float b1 = -1.f;
        #pragma unroll
        for (int e = 0; e < 16; e++) if (p[e] > b1) { b1 = p[e]; i1 = e; }
        int i2 = 0; float b2 = -1.f;
        #pragma unroll
        for (int e = 0; e < 16; e++) if (e != i1 && p[e] > b2) { b2 = p[e]; i2 = e; }
        b1 *= inv; b2 *= inv;
        float den = b1 + b2 + 1e-6f;
        #pragma unroll
        for (int e = 0; e < 16; e++) wsel[warp][e] = 0.f;
        wsel[warp][i1] = (b1 / den) * SCALING;
        wsel[warp][i2] = (b2 / den) * SCALING;
        g_e12[t] = i1 | (i2 << 8);
        int mn = i1 < i2 ? i1 : i2, mx = i1 < i2 ? i2 : i1;
        atomicAdd(&g_pcnt[mn * 16 + mx], 1);
    }
    __syncwarp();
    __half* grow = g_xg + (size_t)t * KTOT + DIN;
    #pragma unroll
    for (int c = lane; c < KG; c += 32) {
        grow[c] = __float2half_rn(wsel[warp][c >> 6] * hsum[warp][c & 63]);
    }
}

// ---------------- sort chain: scan -> scatter -> tile masks -------------------
__global__ void scan_kernel() {
    if (threadIdx.x == 0) {
        int s = 0;
        for (int k = 0; k < 256; k++) { int c = g_pcnt[k]; g_pcnt[k] = s; s += c; }
    }
}
__global__ void scatter_kernel() {
    int t = blockIdx.x * blockDim.x + threadIdx.x;
    int e12 = g_e12[t];
    int e1 = e12 & 255, e2 = (e12 >> 8) & 255;
    int mn = e1 < e2 ? e1 : e2, mx = e1 < e2 ? e2 : e1;
    int pos = atomicAdd(&g_pcnt[mn * 16 + mx], 1);
    g_order[pos] = t;
}
__global__ void tilemask_kernel() {
    __shared__ int bm;
    int b = blockIdx.x, tid = threadIdx.x;
    if (tid == 0) bm = 0;
    __syncthreads();
    int e12 = g_e12[g_order[b * 128 + tid]];
    atomicOr(&bm, (1 << (e12 & 255)) | (1 << ((e12 >> 8) & 255)));
    __syncthreads();
    if (tid == 0) {
        int n = 64;
        for (int k = 0; k < 64; k++) g_chunks[b][k] = k;
        int m = bm;
        for (int e = 0; e < 16; e++)
            if ((m >> e) & 1) g_chunks[b][n++] = 64 + e;
        g_nchunks[b] = n;
    }
}

// ---------------- common GEMM macros ------------------------------------------
#define CPASYNC(dst, src) \
    asm volatile("cp.async.cg.shared.global [%0], [%1], 16;\n" :: "r"(dst), "l"(src))
#define LDSM4(d, addr) \
    asm volatile("ldmatrix.sync.aligned.m8n8.x4.shared.b16 {%0,%1,%2,%3}, [%4];" \
        : "=r"((d)[0]), "=r"((d)[1]), "=r"((d)[2]), "=r"((d)[3]) : "r"(addr))
#define MMA16816(c, a, b) \
    asm volatile("mma.sync.aligned.m16n8k16.row.col.f32.f16.f16.f32 " \
        "{%0,%1,%2,%3}, {%4,%5,%6,%7}, {%8,%9}, {%0,%1,%2,%3};" \
        : "+f"((c)[0]), "+f"((c)[1]), "+f"((c)[2]), "+f"((c)[3]) \
        : "r"((a)[0]), "r"((a)[1]), "r"((a)[2]), "r"((a)[3]), "r"((b)[0]), "r"((b)[1]))

extern __shared__ __align__(128) unsigned char smem_buf[];

// ---------------- small GEMM: 128x128 tile, K32 chunks (split-K 8) ------------
#define LDT1     40
#define TILEH1   (128 * LDT1)
#define STAGEH1  (2 * TILEH1)
#define SMEM1    (3 * STAGEH1 * 2)          // 61440

__global__ __launch_bounds__(256, 2)
void gemm128_kernel(const __half* __restrict__ A, int lda,
                    const __half* __restrict__ B, int ldb,
                    float* __restrict__ C, int ldc, int Kdim)
{
    const int tid = threadIdx.x, lane = tid & 31, warp = tid >> 5;
    const int wm = warp >> 2, wn = warp & 3;
    const int bm = blockIdx.y << 7;
    const uint32_t smbase = smem_u32(smem_buf);

    const int koff = blockIdx.z * Kdim;
    A += koff; B += koff;
    C += (size_t)blockIdx.z * M_TOK * ldc;

    const int r0 = tid >> 2, q0 = (tid & 3) << 3, r1 = r0 + 64;
    const uint32_t ob0 = (uint32_t)(r0 * LDT1 + q0) * 2;
    const uint32_t ob1 = (uint32_t)(r1 * LDT1 + q0) * 2;

    const __half* gA0 = A + (size_t)(bm + r0) * lda + q0;
    const __half* gA1 = A + (size_t)(bm + r1) * lda + q0;
    const __half* gB0 = B + (size_t)r0 * ldb + q0;
    const __half* gB1 = B + (size_t)r1 * ldb + q0;

    auto issue_stage = [&](int st, int k0) {
        uint32_t sb = smbase + (uint32_t)st * (STAGEH1 * 2);
        CPASYNC(sb + ob0, gA0 + k0);
        CPASYNC(sb + ob1, gA1 + k0);
        CPASYNC(sb + TILEH1 * 2 + ob0, gB0 + k0);
        CPASYNC(sb + TILEH1 * 2 + ob1, gB1 + k0);
        asm volatile("cp.async.commit_group;\n" ::);
    };

    const uint32_t aBase = (uint32_t)((wm * 64 + (lane & 15)) * LDT1 + ((lane >> 4) << 3));
    const uint32_t bBase = (uint32_t)((wn * 32 + ((lane >> 4) << 3) + (lane & 7)) * LDT1
                                      + (((lane >> 3) & 1) << 3));
    float acc[4][4][4] = {};
    const int nk = Kdim >> 5;

    issue_stage(0, 0);
    if (nk > 1) issue_stage(1, 32);

    for (int kt = 0; kt < nk; kt++) {
        if (kt + 1 < nk) {
            asm volatile("cp.async.wait_group 1;\n" ::: "memory");
        } else {
            asm volatile("cp.async.wait_group 0;\n" ::: "memory");
        }
        __syncthreads();
        if (kt + 2 < nk) issue_stage((kt + 2) % 3, (kt + 2) << 5);

        uint32_t sb = smbase + (uint32_t)(kt % 3) * (STAGEH1 * 2);
        #pragma unroll
        for (int kk = 0; kk < 32; kk += 16) {
            uint32_t a[4][4], b[4][2];
            #pragma unroll
            for (int mi = 0; mi < 4; mi++)
                LDSM4(a[mi], sb + (aBase + mi * (16 * LDT1) + kk) * 2);
            #pragma unroll
            for (int h = 0; h < 2; h++) {
                uint32_t t4[4];
                LDSM4(t4, sb + TILEH1 * 2 + (bBase + h * (16 * LDT1) + kk) * 2);
                b[2*h][0] = t4[0]; b[2*h][1] = t4[1];
                b[2*h+1][0] = t4[2]; b[2*h+1][1] = t4[3];
            }
            #pragma unroll
            for (int mi = 0; mi < 4; mi++)
                #pragma unroll
                for (int nj = 0; nj < 4; nj++)
                    MMA16816(acc[mi][nj], a[mi], b[nj]);
        }
    }

    const int tr = lane >> 2, tc2 = (lane & 3) << 1;
    #pragma unroll
    for (int mi = 0; mi < 4; mi++) {
        int row = bm + wm * 64 + mi * 16 + tr;
        #pragma unroll
        for (int nj = 0; nj < 4; nj++) {
            int col = wn * 32 + nj * 8 + tc2;
            *(float2*)(C + (size_t)row * ldc + col) = make_float2(acc[mi][nj][0], acc[mi][nj][1]);
            *(float2*)(C + (size_t)(row + 8) * ldc + col) = make_float2(acc[mi][nj][2], acc[mi][nj][3]);
        }
    }
}

// ---------------- main GEMM: sorted-gather, chunk-skipping, K64 chunks --------
#define LDT2     72
#define TILEH2   (128 * LDT2)
#define STAGE2B  (2 * TILEH2 * 2)           // 36864 B per stage
#define IDS2_OFF (3 * STAGE2B)              // 110592
#define CHK_OFF  (IDS2_OFF + 512)
#define SMEM2    (CHK_OFF + 320)            // 111424 B (2 CTAs/SM = 217.6KB)

__global__ __launch_bounds__(256, 2)
void gemm_main_kernel(const __half* __restrict__ A,
                      const __half* __restrict__ B,
                      float* __restrict__ C,
                      const float* __restrict__ bias)
{
    const int tid = threadIdx.x, lane = tid & 31, warp = tid >> 5;
    const int wm = warp >> 2, wn = warp & 3;
    const int mt = blockIdx.y, bn = blockIdx.x << 7;
    const uint32_t smbase = smem_u32(smem_buf);
    int* ids = (int*)(smem_buf + IDS2_OFF);
    int* chk = (int*)(smem_buf + CHK_OFF);

    if (tid < 128) ids[tid] = g_order[mt * 128 + tid];
    else if (tid < 208) chk[tid - 128] = g_chunks[mt][tid - 128];
    __syncthreads();
    const int nk = g_nchunks[mt];

    uint32_t aob[4];
    const __half *gA[4], *gB[4];
    #pragma unroll
    for (int j = 0; j < 4; j++) {
        int c = tid + 256 * j;
        int row = c >> 3, q = (c & 7) << 3;
        aob[j] = (uint32_t)(row * LDT2 + q) * 2;
        gA[j] = A + (size_t)ids[row] * KTOT + q;
        gB[j] = B + (size_t)(bn + row) * KTOT + q;
    }

    auto issue_stage = [&](int st, int k0) {
        uint32_t sb = smbase + (uint32_t)st * STAGE2B;
        #pragma unroll
        for (int j = 0; j < 4; j++) CPASYNC(sb + aob[j], gA[j] + k0);
        uint32_t sb2 = sb + TILEH2 * 2;
        #pragma unroll
        for (int j = 0; j < 4; j++) CPASYNC(sb2 + aob[j], gB[j] + k0);
        asm volatile("cp.async.commit_group;\n" ::);
    };

    const uint32_t aBase = (uint32_t)((wm * 64 + (lane & 15)) * LDT2 + ((lane >> 4) << 3));
    const uint32_t bBase = (uint32_t)((wn * 32 + ((lane >> 4) << 3) + (lane & 7)) * LDT2
                                      + (((lane >> 3) & 1) << 3));
    float acc[4][4][4] = {};

    issue_stage(0, chk[0] << 6);
    issue_stage(1, chk[1] << 6);

    for (int kt = 0; kt < nk; kt++) {
        if (kt + 1 < nk) {
            asm volatile("cp.async.wait_group 1;\n" ::: "memory");
        } else {
            asm volatile("cp.async.wait_group 0;\n" ::: "memory");
        }
        __syncthreads();
        if (kt + 2 < nk) issue_stage((kt + 2) % 3, chk[kt + 2] << 6);

        uint32_t sb = smbase + (uint32_t)(kt % 3) * STAGE2B;
        #pragma unroll
        for (int kk = 0; kk < 64; kk += 16) {
            uint32_t a[4][4], b[4][2];
            #pragma unroll
            for (int mi = 0; mi < 4; mi++)
                LDSM4(a[mi], sb + (aBase + mi * (16 * LDT2) + kk) * 2);
            #pragma unroll
            for (int h = 0; h < 2; h++) {
                uint32_t t4[4];
                LDSM4(t4, sb + TILEH2 * 2 + (bBase + h * (16 * LDT2) + kk) * 2);
                b[2*h][0] = t4[0]; b[2*h][1] = t4[1];
                b[2*h+1][0] = t4[2]; b[2*h+1][1] = t4[3];
            }
            #pragma unroll
            for (int mi = 0; mi < 4; mi++)
                #pragma unroll
                for (int nj = 0; nj < 4; nj++)
                    MMA16816(acc[mi][nj], a[mi], b[nj]);
        }
    }

    // epilogue: scatter rows by token id, add bias
    const int tr = lane >> 2, tc2 = (lane & 3) << 1;
    #pragma unroll
    for (int mi = 0; mi < 4; mi++) {
        int rl = wm * 64 + mi * 16 + tr;
        int tok0 = ids[rl], tok1 = ids[rl + 8];
        #pragma unroll
        for (int nj = 0; nj < 4; nj++) {
            int col = bn + wn * 32 + nj * 8 + tc2;
            float b0 = bias[col], b1 = bias[col + 1];
            *(float2*)(C + (size_t)tok0 * DOUT + col) =
                make_float2(acc[mi][nj][0] + b0, acc[mi][nj][1] + b1);
            *(float2*)(C + (size_t)tok1 * DOUT + col) =
                make_float2(acc[mi][nj][2] + b0, acc[mi][nj][3] + b1);
        }
    }
}

// ---------------- launch ------------------------------------------------------
extern "C" void kernel_launch(void* const* d_in, const int* in_sizes, int n_in,
                              void* d_out, int out_size)
{
    const float* x  = (const float*)d_in[0];
    const float* bw = (const float*)d_in[1];
    const float* bb = (const float*)d_in[2];
    const float* Am = (const float*)d_in[3];
    const float* Bm = (const float*)d_in[4];
    const float* rw = (const float*)d_in[5];
    float* out = (float*)d_out;

    void *pxg, *pwt, *pw2, *phl;
    cudaGetSymbolAddress(&pxg, g_xg);
    cudaGetSymbolAddress(&pwt, g_wt);
    cudaGetSymbolAddress(&pw2, g_w2);
    cudaGetSymbolAddress(&phl, g_hl);

    cudaFuncSetAttribute(gemm128_kernel,
                         cudaFuncAttributeMaxDynamicSharedMemorySize, SMEM1);
    cudaFuncSetAttribute(gemm_main_kernel,
                         cudaFuncAttributeMaxDynamicSharedMemorySize, SMEM2);

    prep_all_kernel<<<NPREP / 256, 256>>>((const float4*)x, bw, Bm, Am, rw);

    // hidden + router logits: [8192,128] = x @ w2^T, split-K 8
    gemm128_kernel<<<dim3(1, 64, NSPLIT), 256, SMEM1>>>(
        (const __half*)pxg, KTOT,
        (const __half*)pw2, DIN,
        (float*)phl, 128, DIN / NSPLIT);

    router_kernel<<<M_TOK / 8, 256>>>();
    scan_kernel<<<1, 32>>>();
    scatter_kernel<<<M_TOK / 256, 256>>>();
    tilemask_kernel<<<64, 128>>>();

    // main fused GEMM, sorted-token gather + zero-chunk skipping
    gemm_main_kernel<<<dim3(DOUT / 128, 64), 256, SMEM2>>>(
        (const __half*)pxg, (const __half*)pwt, out, bb);
}